// round 13
// baseline (speedup 1.0000x reference)
#include <cuda_runtime.h>
#include <cuda_bf16.h>
#include <cstdint>

// ============================================================================
// Mean-field CRF on GB300 (plain sm_103 PTX; mma.sync m16n8k16 bf16).
// K_sp/K_bl symmetric, block-linear chunk-major per 256x256 block pair (p<=q).
// Per iteration: k_soft (softmax -> P A-fragments; zeroes g_red after reading),
// k_gemm (528 pair-CTAs stream K once, 3-stage cp.async pipeline; EVERY warp
// does uniform forward + mirror work per chunk; epilogue = red.global atomics).
//   q = unaries + (A_sp p) K_sp + (A_bl p) K_bl,  A_* = -(compat @ W_*)
// ============================================================================

#define DI __device__ __forceinline__

static constexpr int   NPT   = 8192;
static constexpr int   NC    = 10;
static constexpr int   CP    = 16;
static constexpr int   NBLK  = 32;                       // 256-point blocks
static constexpr int   NPAIR = NBLK * (NBLK + 1) / 2;    // 528
static constexpr int   BLKEL = 256 * 256;
static constexpr float LOG2E = 1.4426950408889634f;
static constexpr float ESP   = LOG2E / 64.0f;
static constexpr float EBL   = LOG2E;

// ---- static device scratch --------------------------------------------------
__device__ __align__(1024) __nv_bfloat16 g_Ksp[(size_t)NPAIR * BLKEL]; // 69 MB
__device__ __align__(1024) __nv_bfloat16 g_Kbl[(size_t)NPAIR * BLKEL]; // 69 MB
__device__ __align__(1024) uint4 g_PF[2][512][32];   // A-fragments per k16 step
__device__ __align__(256)  float g_red[NC * NPT];    // pairwise accumulator
                                                     // invariant: zero between launches

DI float ex2f(float x) { float y; asm("ex2.approx.f32 %0, %1;" : "=f"(y) : "f"(x)); return y; }
DI uint32_t s2u(const void* p) {
    uint32_t a;
    asm("{ .reg .u64 t; cvta.to.shared.u64 t, %1; cvt.u32.u64 %0, t; }" : "=r"(a) : "l"(p));
    return a;
}
DI void cp16(uint32_t s, const void* g) {
    asm volatile("cp.async.cg.shared.global [%0], [%1], 16;" :: "r"(s), "l"(g));
}
DI void redg2(float* a, float x, float y) {
    asm volatile("red.global.add.v2.f32 [%0], {%1, %2};" :: "l"(a), "f"(x), "f"(y) : "memory");
}
DI void mma16816(float* c, const uint32_t* a, uint32_t b0, uint32_t b1) {
    asm volatile(
        "mma.sync.aligned.m16n8k16.row.col.f32.bf16.bf16.f32 "
        "{%0,%1,%2,%3}, {%4,%5,%6,%7}, {%8,%9}, {%0,%1,%2,%3};"
        : "+f"(c[0]), "+f"(c[1]), "+f"(c[2]), "+f"(c[3])
        : "r"(a[0]), "r"(a[1]), "r"(a[2]), "r"(a[3]), "r"(b0), "r"(b1));
}
DI void ldmx4(uint32_t* r, uint32_t addr) {
    asm volatile("ldmatrix.sync.aligned.m8n8.x4.shared.b16 {%0,%1,%2,%3}, [%4];"
                 : "=r"(r[0]), "=r"(r[1]), "=r"(r[2]), "=r"(r[3]) : "r"(addr));
}
DI void ldmx4t(uint32_t* r, uint32_t addr) {
    asm volatile("ldmatrix.sync.aligned.m8n8.x4.trans.shared.b16 {%0,%1,%2,%3}, [%4];"
                 : "=r"(r[0]), "=r"(r[1]), "=r"(r[2]), "=r"(r[3]) : "r"(addr));
}
DI int pair_rank(int p, int q) { return p * (2 * NBLK - p + 1) / 2 + (q - p); }

// ---------------- ncu index shim (launch 0) ----------------------------------
__global__ void k_nop() {}

// ---------------- kernel builder (verified R9) -------------------------------
__global__ __launch_bounds__(256) void k_pairs(const float* __restrict__ feat) {
    int bi = blockIdx.y, bj = blockIdx.x;
    if (!(bj >= bi || (bj == bi - 1 && (bi & 1)))) return;

    __shared__ float sfi[6][128], sfj[6][128], shs[128], shb[128];
    int t = threadIdx.x;
    int i0 = bi * 128, j0 = bj * 128;

    for (int v = t; v < 6 * 128; v += 256) {
        int d = v >> 7, x = v & 127;
        sfi[d][x] = feat[d * NPT + i0 + x];
        sfj[d][x] = feat[d * NPT + j0 + x];
    }
    __syncthreads();
    if (t < 128) {
        float n3 = sfi[0][t] * sfi[0][t] + sfi[1][t] * sfi[1][t] + sfi[2][t] * sfi[2][t];
        float n6 = n3 + sfi[3][t] * sfi[3][t] + sfi[4][t] * sfi[4][t] + sfi[5][t] * sfi[5][t];
        shs[t] = 0.5f * ESP * n3;
        shb[t] = 0.5f * EBL * n6;
    }
    __syncthreads();

    int jl = (t & 15) * 8;
    int it = t >> 4;

    float fj[6][8], hsj[8], hbj[8];
#pragma unroll
    for (int d = 0; d < 6; d++)
#pragma unroll
        for (int u = 0; u < 8; u++) fj[d][u] = sfj[d][jl + u];
#pragma unroll
    for (int u = 0; u < 8; u++) {
        float n3 = fj[0][u] * fj[0][u] + fj[1][u] * fj[1][u] + fj[2][u] * fj[2][u];
        float n6 = n3 + fj[3][u] * fj[3][u] + fj[4][u] * fj[4][u] + fj[5][u] * fj[5][u];
        hsj[u] = 0.5f * ESP * n3;
        hbj[u] = 0.5f * EBL * n6;
    }

    int bmin = bi < bj ? bi : bj, bmax = bi < bj ? bj : bi;
    int p = bmin >> 1, q = bmax >> 1;
    size_t base = (size_t)pair_rank(p, q) * BLKEL;
    int C0 = (bj - 2 * q) * 128 + jl;
    size_t cofs = base + (size_t)(C0 >> 5) * 8192 + (C0 & 31);

#pragma unroll 1
    for (int r = 0; r < 8; r++) {
        int il = it + r * 16;
        float f0 = sfi[0][il], f1 = sfi[1][il], f2 = sfi[2][il];
        float f3 = sfi[3][il], f4 = sfi[4][il], f5 = sfi[5][il];
        float hs = shs[il], hb = shb[il];

        uint32_t ps[4], pb[4];
#pragma unroll
        for (int g2 = 0; g2 < 4; g2++) {
            float vs[2], vb[2];
#pragma unroll
            for (int u2 = 0; u2 < 2; u2++) {
                int u = g2 * 2 + u2;
                float d3 = fmaf(f2, fj[2][u], fmaf(f1, fj[1][u], f0 * fj[0][u]));
                float dh = fmaf(f5, fj[5][u], fmaf(f4, fj[4][u], f3 * fj[3][u]));
                float d6 = d3 + dh;
                vs[u2] = ex2f(fmaf(ESP, d3, -(hs + hsj[u])));
                vb[u2] = ex2f(fmaf(EBL, d6, -(hb + hbj[u])));
            }
            __nv_bfloat162 s2 = __floats2bfloat162_rn(vs[0], vs[1]);
            __nv_bfloat162 b2 = __floats2bfloat162_rn(vb[0], vb[1]);
            ps[g2] = *reinterpret_cast<uint32_t*>(&s2);
            pb[g2] = *reinterpret_cast<uint32_t*>(&b2);
        }
        int R = (bi - 2 * p) * 128 + il;
        size_t off = cofs + (size_t)R * 32;
        *reinterpret_cast<uint4*>(g_Ksp + off) = make_uint4(ps[0], ps[1], ps[2], ps[3]);
        *reinterpret_cast<uint4*>(g_Kbl + off) = make_uint4(pb[0], pb[1], pb[2], pb[3]);
    }
}

// ---------------- softmax + P-fragment writer / final output -----------------
// mode 0: q = unaries -> PF
// mode 1: q = unaries + g_red -> PF   (then zero g_red)
// mode 2: q = unaries + g_red -> out  (then zero g_red)
__global__ __launch_bounds__(128) void k_soft(const float* __restrict__ unaries,
                                              const float* __restrict__ Wsp,
                                              const float* __restrict__ Wbl,
                                              const float* __restrict__ Comp,
                                              float* __restrict__ out,
                                              int mode) {
    __shared__ float sW1[NC * NC], sW2[NC * NC];
    int tl = threadIdx.x;
    int j = blockIdx.x * 128 + tl;

    if (mode != 2 && tl < NC * NC) {
        int c = tl / NC, c2 = tl % NC;
        float s1 = 0.f, s2 = 0.f;
#pragma unroll
        for (int k = 0; k < NC; k++) {
            s1 += Comp[c * NC + k] * Wsp[k * NC + c2];
            s2 += Comp[c * NC + k] * Wbl[k * NC + c2];
        }
        sW1[tl] = -s1;
        sW2[tl] = -s2;
    }
    if (mode != 2) __syncthreads();

    float q[NC];
#pragma unroll
    for (int c = 0; c < NC; c++) q[c] = unaries[(size_t)c * NPT + j];
    if (mode) {
#pragma unroll
        for (int c = 0; c < NC; c++) {
            q[c] += g_red[c * NPT + j];
            g_red[c * NPT + j] = 0.f;      // restore zero invariant
        }
    }
    if (mode == 2) {
#pragma unroll
        for (int c = 0; c < NC; c++) out[(size_t)c * NPT + j] = q[c];
        return;
    }
    float p[NC];
    float m = q[0];
#pragma unroll
    for (int c = 1; c < NC; c++) m = fmaxf(m, q[c]);
    float s = 0.f;
#pragma unroll
    for (int c = 0; c < NC; c++) { p[c] = ex2f((q[c] - m) * LOG2E); s += p[c]; }
    float inv = __fdividef(1.f, s);
#pragma unroll
    for (int c = 0; c < NC; c++) p[c] *= inv;

    int T  = j >> 1, u = j & 1;
    int ks = T >> 3, tq = T & 3;
    int hik = ((T & 7) >= 4) ? 2 : 0;
#pragma unroll
    for (int c16 = 0; c16 < CP; c16++) {
        float v1 = 0.f, v2 = 0.f;
        if (c16 < NC) {
#pragma unroll
            for (int c = 0; c < NC; c++) {
                v1 = fmaf(sW1[c16 * NC + c], p[c], v1);
                v2 = fmaf(sW2[c16 * NC + c], p[c], v2);
            }
        }
        int lane = (c16 & 7) * 4 + tq;
        int reg  = ((c16 >= 8) ? 1 : 0) + hik;
        reinterpret_cast<__nv_bfloat16*>(&g_PF[0][ks][lane])[reg * 2 + u] =
            __float2bfloat16(v1);
        reinterpret_cast<__nv_bfloat16*>(&g_PF[1][ks][lane])[reg * 2 + u] =
            __float2bfloat16(v2);
    }
}

// ---------------- symmetric GEMM: balanced warps, atomic epilogue ------------
// Every warp, every chunk: 4 forward i-tiles (16 mma) + mirror slice
// (jg = w&3, ik-half = w>>2: 16 mma). Warp pairs (w, w^4) share a mirror
// (chunk, jg) accumulator half; atomics complete the sum.
static constexpr int SMEM_GEMM = 3 * 32768;   // 96 KB

__global__ __launch_bounds__(256, 2) void k_gemm() {
    extern __shared__ char dyn[];
    uint32_t sb = s2u(dyn);

    int t = threadIdx.x, w = t >> 5, lane = t & 31, g = lane >> 2, tq = lane & 3;

    int idx = blockIdx.x, p = 0;
    while (idx >= NBLK - p) { idx -= NBLK - p; p++; }
    int q = p + idx;
    bool diag = (p == q);
    size_t base = (size_t)blockIdx.x * BLKEL;

    const char* gsp = reinterpret_cast<const char*>(g_Ksp);
    const char* gbl = reinterpret_cast<const char*>(g_Kbl);

    auto prefetch = [&](int cs) {
        uint32_t bb = sb + (cs % 3) * 32768;
#pragma unroll
        for (int pass = 0; pass < 4; pass++) {
            int e = pass * 2048 + t * 8;
            int r = e >> 5, u = (e & 31) >> 3;
            uint32_t so = (uint32_t)(r * 64 + ((u ^ ((r >> 1) & 3)) * 16));
            size_t go = (base + (size_t)cs * 8192 + e) * 2;
            cp16(bb + so, gsp + go);
            cp16(bb + 16384 + so, gbl + go);
        }
        asm volatile("cp.async.commit_group;" ::: "memory");
    };

    float facc[4][4] = {};
    float macc[8][4] = {};
    int jg  = w & 3;           // mirror j-group
    int ikh = (w >> 2) * 4;    // mirror ik-half base

    prefetch(0);
    prefetch(1);
#pragma unroll 1
    for (int cs = 0; cs < 8; cs++) {
        if (cs == 7) asm volatile("cp.async.wait_group 0;" ::: "memory");
        else         asm volatile("cp.async.wait_group 1;" ::: "memory");
        __syncthreads();
        if (cs < 6) prefetch(cs + 2);
        uint32_t bb = sb + (cs % 3) * 32768;

        // ---- forward: warp's 4 i-tiles x this chunk's 32 j (2 k16 steps) ----
        {
            int ks0 = q * 16 + cs * 2;
            uint4 A1a = g_PF[0][ks0][lane], A1b = g_PF[0][ks0 + 1][lane];
            uint4 A2a = g_PF[1][ks0][lane], A2b = g_PF[1][ks0 + 1][lane];
            int su = lane >> 3;
#pragma unroll
            for (int tt = 0; tt < 4; tt++) {
                int r = (w * 4 + tt) * 8 + (lane & 7);
                uint32_t ad = (uint32_t)(r * 64 + ((su ^ ((r >> 1) & 3)) * 16));
                uint32_t B[4];
                ldmx4(B, bb + ad);
                mma16816(facc[tt], reinterpret_cast<const uint32_t*>(&A1a), B[0], B[1]);
                mma16816(facc[tt], reinterpret_cast<const uint32_t*>(&A1b), B[2], B[3]);
                ldmx4(B, bb + 16384 + ad);
                mma16816(facc[tt], reinterpret_cast<const uint32_t*>(&A2a), B[0], B[1]);
                mma16816(facc[tt], reinterpret_cast<const uint32_t*>(&A2b), B[2], B[3]);
            }
        }

        // ---- mirror: j-group jg, iks [ikh, ikh+4) of this chunk -------------
        if (!diag) {
#pragma unroll
            for (int ii = 0; ii < 4; ii++) {
                int ik = ikh + ii;
                uint4 M1a = g_PF[0][p * 16 + ik * 2][lane];
                uint4 M1b = g_PF[0][p * 16 + ik * 2 + 1][lane];
                uint4 M2a = g_PF[1][p * 16 + ik * 2][lane];
                uint4 M2b = g_PF[1][p * 16 + ik * 2 + 1][lane];
                int r = ik * 32 + (lane >> 3) * 8 + (lane & 7);
                uint32_t ad = (uint32_t)(r * 64 + ((jg ^ ((r >> 1) & 3)) * 16));
                uint32_t B[4];
                ldmx4t(B, bb + ad);
                mma16816(macc[cs], reinterpret_cast<const uint32_t*>(&M1a), B[0], B[1]);
                mma16816(macc[cs], reinterpret_cast<const uint32_t*>(&M1b), B[2], B[3]);
                ldmx4t(B, bb + 16384 + ad);
                mma16816(macc[cs], reinterpret_cast<const uint32_t*>(&M2a), B[0], B[1]);
                mma16816(macc[cs], reinterpret_cast<const uint32_t*>(&M2b), B[2], B[3]);
            }
        }
    }

    // ---- epilogue: atomic accumulate into g_red (skip zero class rows) ------
#pragma unroll
    for (int tt = 0; tt < 4; tt++) {
        int i = p * 256 + (w * 4 + tt) * 8 + tq * 2;
        redg2(&g_red[g * NPT + i], facc[tt][0], facc[tt][1]);
        if (g < NC - 8)
            redg2(&g_red[(g + 8) * NPT + i], facc[tt][2], facc[tt][3]);
    }
    if (!diag) {
#pragma unroll
        for (int cs = 0; cs < 8; cs++) {
            int j = q * 256 + cs * 32 + jg * 8 + tq * 2;
            redg2(&g_red[g * NPT + j], macc[cs][0], macc[cs][1]);
            if (g < NC - 8)
                redg2(&g_red[(g + 8) * NPT + j], macc[cs][2], macc[cs][3]);
        }
    }
}

// ---------------- launch ------------------------------------------------------
extern "C" void kernel_launch(void* const* d_in, const int* in_sizes, int n_in,
                              void* d_out, int out_size) {
    const float* unaries = (const float*)d_in[0];
    const float* feat    = (const float*)d_in[1];
    const float* Wsp     = (const float*)d_in[2];
    const float* Wbl     = (const float*)d_in[3];
    const float* Comp    = (const float*)d_in[4];
    float* out = (float*)d_out;

    cudaFuncSetAttribute(k_gemm, cudaFuncAttributeMaxDynamicSharedMemorySize,
                         SMEM_GEMM);

    k_nop<<<1, 32>>>();                                           // 0 (ncu shim)
    k_pairs<<<dim3(64, 64), 256>>>(feat);                         // 1
    k_soft<<<NPT / 128, 128>>>(unaries, Wsp, Wbl, Comp, out, 0);  // 2
    for (int it = 0; it < 5; it++) {
        k_gemm<<<NPAIR, 256, SMEM_GEMM>>>();                      // 3,5,7,9,11 (5 = iter1)
        k_soft<<<NPT / 128, 128>>>(unaries, Wsp, Wbl, Comp, out,
                                   (it == 4) ? 2 : 1);            // 4,6,8,10,12
    }
}

// round 14
// speedup vs baseline: 1.2673x; 1.2673x over previous
#include <cuda_runtime.h>
#include <cuda_bf16.h>
#include <cstdint>

// ============================================================================
// Mean-field CRF on GB300 (plain sm_103 PTX; mma.sync m16n8k16 bf16).
// K_sp/K_bl symmetric, stored FRAGMENT-BLOCKED per 256x256 block pair (p<=q):
// 512B block = (8-i tile) x (32-j superchunk), uint4/lane = B-fragments.
// k_gemm is barrier-free and smem-free: forward B-frags via direct LDG.128;
// mirror B-frags = movmatrix (in-register 8x8 transpose) of the SAME regs.
// Epilogue/mirror results accumulate via red.global into g_red (zero-invariant,
// k_soft reads + rezeroes).  q = unaries + (A_sp p)K_sp + (A_bl p)K_bl.
// ============================================================================

#define DI __device__ __forceinline__

static constexpr int   NPT   = 8192;
static constexpr int   NC    = 10;
static constexpr int   CP    = 16;
static constexpr int   NBLK  = 32;                       // 256-point blocks
static constexpr int   NPAIR = NBLK * (NBLK + 1) / 2;    // 528
static constexpr int   BLKU4 = 8192;                     // uint4 per block pair
static constexpr float LOG2E = 1.4426950408889634f;
static constexpr float ESP   = LOG2E / 64.0f;
static constexpr float EBL   = LOG2E;

// ---- static device scratch --------------------------------------------------
__device__ __align__(1024) __nv_bfloat16 g_Ksp[(size_t)NPAIR * BLKU4 * 8]; // 69 MB
__device__ __align__(1024) __nv_bfloat16 g_Kbl[(size_t)NPAIR * BLKU4 * 8]; // 69 MB
__device__ __align__(1024) uint4 g_PF[2][512][32];   // A-fragments per k16 step
__device__ __align__(256)  float g_red[NC * NPT];    // pairwise accumulator
                                                     // invariant: zero between launches

DI float ex2f(float x) { float y; asm("ex2.approx.f32 %0, %1;" : "=f"(y) : "f"(x)); return y; }
DI void redg2(float* a, float x, float y) {
    asm volatile("red.global.add.v2.f32 [%0], {%1, %2};" :: "l"(a), "f"(x), "f"(y) : "memory");
}
DI void mma16816(float* c, const uint32_t* a, uint32_t b0, uint32_t b1) {
    asm volatile(
        "mma.sync.aligned.m16n8k16.row.col.f32.bf16.bf16.f32 "
        "{%0,%1,%2,%3}, {%4,%5,%6,%7}, {%8,%9}, {%0,%1,%2,%3};"
        : "+f"(c[0]), "+f"(c[1]), "+f"(c[2]), "+f"(c[3])
        : "r"(a[0]), "r"(a[1]), "r"(a[2]), "r"(a[3]), "r"(b0), "r"(b1));
}
DI uint32_t movm(uint32_t a) {
    uint32_t d;
    asm volatile("movmatrix.sync.aligned.m8n8.trans.b16 %0, %1;" : "=r"(d) : "r"(a));
    return d;
}
DI int pair_rank(int p, int q) { return p * (2 * NBLK - p + 1) / 2 + (q - p); }

// ---------------- ncu index shim (launch 0) ----------------------------------
__global__ void k_nop() {}

// ---------------- kernel builder: fragment-blocked pair storage --------------
// 128-tile (bi,bj) kept iff bj>=bi or lower tile of a diagonal 256-block.
// Thread mapping + fragment packing lifted from the R2/R5-verified builder.
__global__ __launch_bounds__(256) void k_pairs(const float* __restrict__ feat) {
    int bi = blockIdx.y, bj = blockIdx.x;
    if (!(bj >= bi || (bj == bi - 1 && (bi & 1)))) return;

    __shared__ float sfi[6][128], sfj[6][128], shs[128], shb[128];
    int t = threadIdx.x;
    int i0 = bi * 128, j0 = bj * 128;

    for (int v = t; v < 6 * 128; v += 256) {
        int d = v >> 7, x = v & 127;
        sfi[d][x] = feat[d * NPT + i0 + x];
        sfj[d][x] = feat[d * NPT + j0 + x];
    }
    __syncthreads();
    if (t < 128) {
        float n3 = sfi[0][t] * sfi[0][t] + sfi[1][t] * sfi[1][t] + sfi[2][t] * sfi[2][t];
        float n6 = n3 + sfi[3][t] * sfi[3][t] + sfi[4][t] * sfi[4][t] + sfi[5][t] * sfi[5][t];
        shs[t] = 0.5f * ESP * n3;
        shb[t] = 0.5f * EBL * n6;
    }
    __syncthreads();

    int w = t >> 5, lane = t & 31;
    int ir = lane >> 2, tq = lane & 3;
    int js_local = w & 3;          // superchunk within 128-tile
    int itgrp    = w >> 2;

    int jl[8];
#pragma unroll
    for (int u = 0; u < 8; u++)
        jl[u] = js_local * 32 + tq * 2 + (u & 1) + ((u >> 1) << 3);

    float fj[6][8], hsj[8], hbj[8];
#pragma unroll
    for (int d = 0; d < 6; d++)
#pragma unroll
        for (int u = 0; u < 8; u++) fj[d][u] = sfj[d][jl[u]];
#pragma unroll
    for (int u = 0; u < 8; u++) {
        float n3 = fj[0][u] * fj[0][u] + fj[1][u] * fj[1][u] + fj[2][u] * fj[2][u];
        float n6 = n3 + fj[3][u] * fj[3][u] + fj[4][u] * fj[4][u] + fj[5][u] * fj[5][u];
        hsj[u] = 0.5f * ESP * n3;
        hbj[u] = 0.5f * EBL * n6;
    }

    int P = bi >> 1, Q = bj >> 1;                 // P<=Q for all kept tiles
    size_t base4 = (size_t)pair_rank(P, Q) * BLKU4;
    int js_blk = (bj & 1) * 4 + js_local;         // 0..7

#pragma unroll 1
    for (int r = 0; r < 8; r++) {
        int it_local = r * 2 + itgrp;             // 0..15 within 128-tile
        int il = it_local * 8 + ir;
        float f0 = sfi[0][il], f1 = sfi[1][il], f2 = sfi[2][il];
        float f3 = sfi[3][il], f4 = sfi[4][il], f5 = sfi[5][il];
        float hs = shs[il], hb = shb[il];

        uint32_t ps[4], pb[4];
#pragma unroll
        for (int g2 = 0; g2 < 4; g2++) {
            float vs[2], vb[2];
#pragma unroll
            for (int u2 = 0; u2 < 2; u2++) {
                int u = g2 * 2 + u2;
                float d3 = fmaf(f2, fj[2][u], fmaf(f1, fj[1][u], f0 * fj[0][u]));
                float dh = fmaf(f5, fj[5][u], fmaf(f4, fj[4][u], f3 * fj[3][u]));
                float d6 = d3 + dh;
                vs[u2] = ex2f(fmaf(ESP, d3, -(hs + hsj[u])));
                vb[u2] = ex2f(fmaf(EBL, d6, -(hb + hbj[u])));
            }
            __nv_bfloat162 s2 = __floats2bfloat162_rn(vs[0], vs[1]);
            __nv_bfloat162 b2 = __floats2bfloat162_rn(vb[0], vb[1]);
            ps[g2] = *reinterpret_cast<uint32_t*>(&s2);
            pb[g2] = *reinterpret_cast<uint32_t*>(&b2);
        }
        int it_blk = (bi & 1) * 16 + it_local;    // 0..31 within 256-block
        size_t u4 = base4 + ((size_t)it_blk * 8 + js_blk) * 32 + lane;
        reinterpret_cast<uint4*>(g_Ksp)[u4] = make_uint4(ps[0], ps[1], ps[2], ps[3]);
        reinterpret_cast<uint4*>(g_Kbl)[u4] = make_uint4(pb[0], pb[1], pb[2], pb[3]);
    }
}

// ---------------- softmax + P-fragment writer / final output -----------------
// mode 0: q = unaries -> PF
// mode 1: q = unaries + g_red -> PF   (then zero g_red)
// mode 2: q = unaries + g_red -> out  (then zero g_red)
__global__ __launch_bounds__(128) void k_soft(const float* __restrict__ unaries,
                                              const float* __restrict__ Wsp,
                                              const float* __restrict__ Wbl,
                                              const float* __restrict__ Comp,
                                              float* __restrict__ out,
                                              int mode) {
    __shared__ float sW1[NC * NC], sW2[NC * NC];
    int tl = threadIdx.x;
    int j = blockIdx.x * 128 + tl;

    if (mode != 2 && tl < NC * NC) {
        int c = tl / NC, c2 = tl % NC;
        float s1 = 0.f, s2 = 0.f;
#pragma unroll
        for (int k = 0; k < NC; k++) {
            s1 += Comp[c * NC + k] * Wsp[k * NC + c2];
            s2 += Comp[c * NC + k] * Wbl[k * NC + c2];
        }
        sW1[tl] = -s1;
        sW2[tl] = -s2;
    }
    if (mode != 2) __syncthreads();

    float q[NC];
#pragma unroll
    for (int c = 0; c < NC; c++) q[c] = unaries[(size_t)c * NPT + j];
    if (mode) {
#pragma unroll
        for (int c = 0; c < NC; c++) {
            q[c] += g_red[c * NPT + j];
            g_red[c * NPT + j] = 0.f;      // restore zero invariant
        }
    }
    if (mode == 2) {
#pragma unroll
        for (int c = 0; c < NC; c++) out[(size_t)c * NPT + j] = q[c];
        return;
    }
    float p[NC];
    float m = q[0];
#pragma unroll
    for (int c = 1; c < NC; c++) m = fmaxf(m, q[c]);
    float s = 0.f;
#pragma unroll
    for (int c = 0; c < NC; c++) { p[c] = ex2f((q[c] - m) * LOG2E); s += p[c]; }
    float inv = __fdividef(1.f, s);
#pragma unroll
    for (int c = 0; c < NC; c++) p[c] *= inv;

    int T  = j >> 1, u = j & 1;
    int ks = T >> 3, tq = T & 3;
    int hik = ((T & 7) >= 4) ? 2 : 0;
#pragma unroll
    for (int c16 = 0; c16 < CP; c16++) {
        float v1 = 0.f, v2 = 0.f;
        if (c16 < NC) {
#pragma unroll
            for (int c = 0; c < NC; c++) {
                v1 = fmaf(sW1[c16 * NC + c], p[c], v1);
                v2 = fmaf(sW2[c16 * NC + c], p[c], v2);
            }
        }
        int lane = (c16 & 7) * 4 + tq;
        int reg  = ((c16 >= 8) ? 1 : 0) + hik;
        reinterpret_cast<__nv_bfloat16*>(&g_PF[0][ks][lane])[reg * 2 + u] =
            __float2bfloat16(v1);
        reinterpret_cast<__nv_bfloat16*>(&g_PF[1][ks][lane])[reg * 2 + u] =
            __float2bfloat16(v2);
    }
}

// ---------------- symmetric GEMM: barrier-free, movmatrix mirror -------------
// CTA = pair (p<=q), 8 warps. Warp owns i-tiles w*4..w*4+3 (32 i of p-block),
// streams 8 superchunks (32 j each) of q-block. Forward: direct-LDG B-frags.
// Mirror: movmatrix of the same regs -> Kt frags; per-jo atomics.
__global__ __launch_bounds__(256, 2) void k_gemm() {
    int t = threadIdx.x, w = t >> 5, lane = t & 31, g = lane >> 2, tq = lane & 3;

    int idx = blockIdx.x, p = 0;
    while (idx >= NBLK - p) { idx -= NBLK - p; p++; }
    int q = p + idx;
    bool diag = (p == q);

    const uint4* K1 = reinterpret_cast<const uint4*>(g_Ksp) + (size_t)blockIdx.x * BLKU4;
    const uint4* K2 = reinterpret_cast<const uint4*>(g_Kbl) + (size_t)blockIdx.x * BLKU4;

    // mirror A-fragments: constant across chunks (k16 groups w*2, w*2+1 of p)
    uint4 MA1[2], MA2[2];
#pragma unroll
    for (int s = 0; s < 2; s++) {
        MA1[s] = g_PF[0][p * 16 + w * 2 + s][lane];
        MA2[s] = g_PF[1][p * 16 + w * 2 + s][lane];
    }

    float facc[4][4] = {};

#pragma unroll 1
    for (int cs = 0; cs < 8; cs++) {
        // forward A-fragments for this chunk's 32 j (two k16 steps)
        int ks0 = q * 16 + cs * 2;
        uint4 A1a = g_PF[0][ks0][lane], A1b = g_PF[0][ks0 + 1][lane];
        uint4 A2a = g_PF[1][ks0][lane], A2b = g_PF[1][ks0 + 1][lane];

        // front-batched B loads: 8 contiguous 512B LDG.128 per warp
        uint4 B1[4], B2[4];
#pragma unroll
        for (int tt = 0; tt < 4; tt++) {
            size_t u4 = ((size_t)(w * 4 + tt) * 8 + cs) * 32 + lane;
            B1[tt] = K1[u4];
            B2[tt] = K2[u4];
        }

        // ---- forward: out[i in p-block] += P(q) . K ----
#pragma unroll
        for (int tt = 0; tt < 4; tt++) {
            mma16816(facc[tt], reinterpret_cast<const uint32_t*>(&A1a), B1[tt].x, B1[tt].y);
            mma16816(facc[tt], reinterpret_cast<const uint32_t*>(&A1b), B1[tt].z, B1[tt].w);
            mma16816(facc[tt], reinterpret_cast<const uint32_t*>(&A2a), B2[tt].x, B2[tt].y);
            mma16816(facc[tt], reinterpret_cast<const uint32_t*>(&A2b), B2[tt].z, B2[tt].w);
        }

        // ---- mirror: out[j in q-block] += P(p) . K^T  (movmatrix transpose) --
        if (!diag) {
            uint32_t T1[4][4], T2[4][4];
#pragma unroll
            for (int tt = 0; tt < 4; tt++) {
                const uint32_t* b1 = reinterpret_cast<const uint32_t*>(&B1[tt]);
                const uint32_t* b2 = reinterpret_cast<const uint32_t*>(&B2[tt]);
#pragma unroll
                for (int jo = 0; jo < 4; jo++) {
                    T1[tt][jo] = movm(b1[jo]);
                    T2[tt][jo] = movm(b2[jo]);
                }
            }
#pragma unroll
            for (int jo = 0; jo < 4; jo++) {
                float macc[4] = {0.f, 0.f, 0.f, 0.f};
                mma16816(macc, reinterpret_cast<const uint32_t*>(&MA1[0]), T1[0][jo], T1[1][jo]);
                mma16816(macc, reinterpret_cast<const uint32_t*>(&MA1[1]), T1[2][jo], T1[3][jo]);
                mma16816(macc, reinterpret_cast<const uint32_t*>(&MA2[0]), T2[0][jo], T2[1][jo]);
                mma16816(macc, reinterpret_cast<const uint32_t*>(&MA2[1]), T2[2][jo], T2[3][jo]);
                int j = q * 256 + cs * 32 + jo * 8 + tq * 2;
                redg2(&g_red[g * NPT + j], macc[0], macc[1]);
                if (g < NC - 8)
                    redg2(&g_red[(g + 8) * NPT + j], macc[2], macc[3]);
            }
        }
    }

    // ---- forward epilogue ----
#pragma unroll
    for (int tt = 0; tt < 4; tt++) {
        int i = p * 256 + (w * 4 + tt) * 8 + tq * 2;
        redg2(&g_red[g * NPT + i], facc[tt][0], facc[tt][1]);
        if (g < NC - 8)
            redg2(&g_red[(g + 8) * NPT + i], facc[tt][2], facc[tt][3]);
    }
}

// ---------------- launch ------------------------------------------------------
extern "C" void kernel_launch(void* const* d_in, const int* in_sizes, int n_in,
                              void* d_out, int out_size) {
    const float* unaries = (const float*)d_in[0];
    const float* feat    = (const float*)d_in[1];
    const float* Wsp     = (const float*)d_in[2];
    const float* Wbl     = (const float*)d_in[3];
    const float* Comp    = (const float*)d_in[4];
    float* out = (float*)d_out;

    k_nop<<<1, 32>>>();                                           // 0 (ncu shim)
    k_pairs<<<dim3(64, 64), 256>>>(feat);                         // 1
    k_soft<<<NPT / 128, 128>>>(unaries, Wsp, Wbl, Comp, out, 0);  // 2
    for (int it = 0; it < 5; it++) {
        k_gemm<<<NPAIR, 256>>>();                                 // 3,5,7,9,11 (5 = iter1)
        k_soft<<<NPT / 128, 128>>>(unaries, Wsp, Wbl, Comp, out,
                                   (it == 4) ? 2 : 1);            // 4,6,8,10,12
    }
}